// round 5
// baseline (speedup 1.0000x reference)
#include <cuda_runtime.h>
#include <cstdint>

#define NN      10000       // nodes
#define NBATCH  16          // batch
#define FDIM    128         // feature dim (64 input + 64 hidden)
#define ROWSZ   2048        // NBATCH * FDIM, floats per node-row
#define PROWSZ  1024        // packed (bf16-pair) uints per node-row
#define NE      160000      // edges
#define ODIM    128         // output dim
#define KDIM    384         // FDIM * 3 matrices
#define KPAIRS  192         // KDIM / 2
#define MROWS   160000      // NBATCH * NN
#define INSZ    640000      // NN * 64, per-batch stride of inputs/state

// ---- scratch (static device globals; no allocation) ----
__device__ float    g_x0[NN * ROWSZ];
__device__ float    g_x1[NN * ROWSZ];
__device__ unsigned g_x0h[NN * PROWSZ];
__device__ unsigned g_x0l[NN * PROWSZ];
__device__ unsigned g_x1h[NN * PROWSZ];
__device__ unsigned g_x1l[NN * PROWSZ];
__device__ unsigned g_x2h[NN * PROWSZ];
__device__ unsigned g_x2l[NN * PROWSZ];
__device__ unsigned g_wph[KPAIRS * ODIM];
__device__ unsigned g_wpl[KPAIRS * ODIM];
__device__ int      g_rowptr[NN + 1];

// pack two fp32 (even k, odd k) into bf16x2 hi + exact-residual bf16x2 lo
__device__ __forceinline__ void pack2(float e, float o, unsigned& h, unsigned& l) {
    asm("cvt.rn.bf16x2.f32 %0, %1, %2;" : "=r"(h) : "f"(o), "f"(e));
    float he = __uint_as_float(h << 16);
    float ho = __uint_as_float(h & 0xffff0000u);
    asm("cvt.rn.bf16x2.f32 %0, %1, %2;" : "=r"(l) : "f"(o - ho), "f"(e - he));
}

// ============================================================
// Kernel 1: build x0[n][b][f] (fp32 + packed hi/lo bf16 pairs)
// ============================================================
__global__ void build_x0_kernel(const float* __restrict__ in,
                                const float* __restrict__ st) {
    int id = blockIdx.x * blockDim.x + threadIdx.x;   // float4 units
    if (id >= NN * ROWSZ / 4) return;
    int f4 = id & 31;            // 32 float4 per (n,b)
    int b  = (id >> 5) & 15;
    int n  = id >> 9;
    int f  = f4 << 2;
    const float* src = (f < 64) ? (in + b * INSZ + n * 64 + f)
                                : (st + b * INSZ + n * 64 + (f - 64));
    float4 v = *reinterpret_cast<const float4*>(src);
    reinterpret_cast<float4*>(g_x0)[id] = v;
    uint2 h, l;
    pack2(v.x, v.y, h.x, l.x);
    pack2(v.z, v.w, h.y, l.y);
    reinterpret_cast<uint2*>(g_x0h)[id] = h;
    reinterpret_cast<uint2*>(g_x0l)[id] = l;
}

// ============================================================
// Kernel 2: CSR row pointers from sorted COO rows
// ============================================================
__global__ void build_rowptr_kernel(const int* __restrict__ rows) {
    int e = blockIdx.x * blockDim.x + threadIdx.x;
    if (e >= NE) return;
    int r = rows[e];
    int rprev = (e == 0) ? -1 : rows[e - 1];
    for (int rr = rprev + 1; rr <= r; ++rr) g_rowptr[rr] = e;
    if (e == NE - 1) {
        for (int rr = r + 1; rr <= NN; ++rr) g_rowptr[rr] = NE;
    }
}

// ============================================================
// Kernel 3: weight W[f*3+m][o] -> packed W'[kp][o] hi/lo
//   k = m*128+f ; pair (2kp, 2kp+1) always within one matrix m
// ============================================================
__global__ void reorder_w_kernel(const float* __restrict__ w) {
    int id = blockIdx.x * blockDim.x + threadIdx.x;  // 192*128 = 24576
    if (id >= KPAIRS * ODIM) return;
    int o  = id & 127;
    int kp = id >> 7;            // 0..191
    int m  = kp >> 6;            // matrix
    int fe = (kp & 63) << 1;     // even feature
    float we = w[(fe * 3 + m) * ODIM + o];
    float wo = w[((fe + 1) * 3 + m) * ODIM + o];
    unsigned h, l;
    pack2(we, wo, h, l);
    g_wph[id] = h;
    g_wpl[id] = l;
}

// ============================================================
// Kernel 4: SpMM (CSR, 2 blocks per row, 256 thr x 4 floats)
//   unrolled x4, 4 accumulators (MLP=4)
//   mode 0:  x1 = S x0            -> fp32 + hi/lo
//   mode 1:  x2 = 2 S x1 - x0     -> hi/lo only
// ============================================================
__global__ __launch_bounds__(256) void spmm_kernel(const int* __restrict__ cols,
                                                   const float* __restrict__ vals,
                                                   int mode) {
    const float* __restrict__ z = mode ? g_x1 : g_x0;
    const float alpha           = mode ? 2.0f : 1.0f;

    int r    = blockIdx.x >> 1;          // node row
    int half = blockIdx.x & 1;           // which 1024-float half
    int t    = threadIdx.x + half * 256; // float4 index within row: 0..511
    int e0 = g_rowptr[r];
    int e1 = g_rowptr[r + 1];
    int base = r * ROWSZ;

    float4 a0 = make_float4(0.f, 0.f, 0.f, 0.f);
    float4 a1 = a0, a2 = a0, a3 = a0;
    if (mode) {
        float4 s = reinterpret_cast<const float4*>(g_x0 + base)[t];
        a0.x = -s.x; a0.y = -s.y; a0.z = -s.z; a0.w = -s.w;
    }

    const float4* z4 = reinterpret_cast<const float4*>(z);
    int e = e0;
    for (; e + 3 < e1; e += 4) {
        int   c0 = __ldg(&cols[e]);
        int   c1 = __ldg(&cols[e + 1]);
        int   c2 = __ldg(&cols[e + 2]);
        int   c3 = __ldg(&cols[e + 3]);
        float v0 = alpha * __ldg(&vals[e]);
        float v1 = alpha * __ldg(&vals[e + 1]);
        float v2 = alpha * __ldg(&vals[e + 2]);
        float v3 = alpha * __ldg(&vals[e + 3]);
        float4 p0 = z4[c0 * 512 + t];
        float4 p1 = z4[c1 * 512 + t];
        float4 p2 = z4[c2 * 512 + t];
        float4 p3 = z4[c3 * 512 + t];
        a0.x += v0 * p0.x; a0.y += v0 * p0.y; a0.z += v0 * p0.z; a0.w += v0 * p0.w;
        a1.x += v1 * p1.x; a1.y += v1 * p1.y; a1.z += v1 * p1.z; a1.w += v1 * p1.w;
        a2.x += v2 * p2.x; a2.y += v2 * p2.y; a2.z += v2 * p2.z; a2.w += v2 * p2.w;
        a3.x += v3 * p3.x; a3.y += v3 * p3.y; a3.z += v3 * p3.z; a3.w += v3 * p3.w;
    }
    for (; e < e1; ++e) {
        int   c0 = __ldg(&cols[e]);
        float v0 = alpha * __ldg(&vals[e]);
        float4 p0 = z4[c0 * 512 + t];
        a0.x += v0 * p0.x; a0.y += v0 * p0.y; a0.z += v0 * p0.z; a0.w += v0 * p0.w;
    }
    a0.x += a1.x + a2.x + a3.x;
    a0.y += a1.y + a2.y + a3.y;
    a0.z += a1.z + a2.z + a3.z;
    a0.w += a1.w + a2.w + a3.w;

    uint2 h, l;
    pack2(a0.x, a0.y, h.x, l.x);
    pack2(a0.z, a0.w, h.y, l.y);
    int pidx = r * (PROWSZ / 2) + t;     // uint2 index into packed row
    if (mode) {
        reinterpret_cast<uint2*>(g_x2h)[pidx] = h;
        reinterpret_cast<uint2*>(g_x2l)[pidx] = l;
    } else {
        reinterpret_cast<float4*>(g_x1 + base)[t] = a0;
        reinterpret_cast<uint2*>(g_x1h)[pidx] = h;
        reinterpret_cast<uint2*>(g_x1l)[pidx] = l;
    }
}

__device__ __forceinline__ void mma16816(float c[4], const unsigned a[4], const unsigned b[2]) {
    asm("mma.sync.aligned.m16n8k16.row.col.f32.bf16.bf16.f32 "
        "{%0,%1,%2,%3},{%4,%5,%6,%7},{%8,%9},{%0,%1,%2,%3};"
        : "+f"(c[0]), "+f"(c[1]), "+f"(c[2]), "+f"(c[3])
        : "r"(a[0]), "r"(a[1]), "r"(a[2]), "r"(a[3]), "r"(b[0]), "r"(b[1]));
}

// ============================================================
// Kernel 5: GEMM  out[r, o] = bias[o] + sum_k A[r,k] * W'[k,o]
//   BM=128 BN=128 BK=16 (8 kpairs), 256 threads (8 warps 2x4)
//   pre-split bf16 hi/lo operands, 3xMMA per tile, no cvt in loop
// ============================================================
__global__ __launch_bounds__(256) void gemm_kernel(const float* __restrict__ bias,
                                                   float* __restrict__ out) {
    __shared__ unsigned Ah[2][8][136], Al[2][8][136];   // [kpair][m], pad 136
    __shared__ unsigned Bh[2][8][136], Bl[2][8][136];   // [kpair][n]

    const int tid  = threadIdx.x;
    const int r0   = blockIdx.x * 128;
    const int lane = tid & 31;
    const int wid  = tid >> 5;
    const int wm   = wid & 1;          // warp row  (64 rows each)
    const int wn   = wid >> 1;         // warp col  (32 cols each)
    const int rp   = lane >> 2;        // 0..7
    const int kp   = lane & 3;         // kpair low index
    const int c2   = kp << 1;          // even col within k16

    // ---- staging indices ----
    const int rowA0 = tid >> 2;          // 0..63
    const int rowA1 = rowA0 + 64;
    const int kq    = (tid & 3) << 1;    // kpair offset 0,2,4,6

    int rg0 = r0 + rowA0;
    int b0  = rg0 / NN;
    int baseP0 = (rg0 - b0 * NN) * PROWSZ + b0 * 64;
    int rg1 = r0 + rowA1;
    int b1  = rg1 / NN;
    int baseP1 = (rg1 - b1 * NN) * PROWSZ + b1 * 64;

    const int krow = tid >> 5;           // 0..7 (kpair row for B)
    const int o4   = (tid & 31) << 2;    // 0..124

    float C[4][4][4];
    #pragma unroll
    for (int i = 0; i < 4; ++i)
        #pragma unroll
        for (int j = 0; j < 4; ++j)
            #pragma unroll
            for (int q = 0; q < 4; ++q)
                C[i][j][q] = 0.f;

    // ---- prologue: chunk 0 (m=0, kpair base 0) ----
    {
        uint2 h0 = *reinterpret_cast<const uint2*>(g_x0h + baseP0 + kq);
        uint2 l0 = *reinterpret_cast<const uint2*>(g_x0l + baseP0 + kq);
        uint2 h1 = *reinterpret_cast<const uint2*>(g_x0h + baseP1 + kq);
        uint2 l1 = *reinterpret_cast<const uint2*>(g_x0l + baseP1 + kq);
        Ah[0][kq][rowA0] = h0.x; Ah[0][kq + 1][rowA0] = h0.y;
        Al[0][kq][rowA0] = l0.x; Al[0][kq + 1][rowA0] = l0.y;
        Ah[0][kq][rowA1] = h1.x; Ah[0][kq + 1][rowA1] = h1.y;
        Al[0][kq][rowA1] = l1.x; Al[0][kq + 1][rowA1] = l1.y;
        uint4 wh = *reinterpret_cast<const uint4*>(g_wph + krow * ODIM + o4);
        uint4 wl = *reinterpret_cast<const uint4*>(g_wpl + krow * ODIM + o4);
        *reinterpret_cast<uint4*>(&Bh[0][krow][o4]) = wh;
        *reinterpret_cast<uint4*>(&Bl[0][krow][o4]) = wl;
    }
    __syncthreads();

    #pragma unroll 1
    for (int kc = 0; kc < 24; ++kc) {
        const int cur = kc & 1;
        uint2 nh0, nl0, nh1, nl1;
        uint4 nwh, nwl;
        if (kc < 23) {
            int kn = kc + 1;
            int m  = kn >> 3;
            int kpb = (kn & 7) << 3;           // kpair base within matrix
            const unsigned* Xh = (m == 0) ? g_x0h : (m == 1) ? g_x1h : g_x2h;
            const unsigned* Xl = (m == 0) ? g_x0l : (m == 1) ? g_x1l : g_x2l;
            nh0 = *reinterpret_cast<const uint2*>(Xh + baseP0 + kpb + kq);
            nl0 = *reinterpret_cast<const uint2*>(Xl + baseP0 + kpb + kq);
            nh1 = *reinterpret_cast<const uint2*>(Xh + baseP1 + kpb + kq);
            nl1 = *reinterpret_cast<const uint2*>(Xl + baseP1 + kpb + kq);
            int kr = (kn << 3) + krow;         // global kpair row for B
            nwh = *reinterpret_cast<const uint4*>(g_wph + kr * ODIM + o4);
            nwl = *reinterpret_cast<const uint4*>(g_wpl + kr * ODIM + o4);
        }

        // ---- B fragments (all j) ----
        unsigned Bfh[4][2], Bfl[4][2];
        #pragma unroll
        for (int j = 0; j < 4; ++j) {
            int n = wn * 32 + j * 8 + rp;
            Bfh[j][0] = Bh[cur][kp][n];     Bfh[j][1] = Bh[cur][kp + 4][n];
            Bfl[j][0] = Bl[cur][kp][n];     Bfl[j][1] = Bl[cur][kp + 4][n];
        }

        // ---- per-i: A fragment + 3xMMA row ----
        #pragma unroll
        for (int i = 0; i < 4; ++i) {
            int r = wm * 64 + i * 16 + rp;
            unsigned Afh[4], Afl[4];
            Afh[0] = Ah[cur][kp][r];      Afh[1] = Ah[cur][kp][r + 8];
            Afh[2] = Ah[cur][kp + 4][r];  Afh[3] = Ah[cur][kp + 4][r + 8];
            Afl[0] = Al[cur][kp][r];      Afl[1] = Al[cur][kp][r + 8];
            Afl[2] = Al[cur][kp + 4][r];  Afl[3] = Al[cur][kp + 4][r + 8];
            #pragma unroll
            for (int j = 0; j < 4; ++j) {
                mma16816(C[i][j], Afl, Bfh[j]);
                mma16816(C[i][j], Afh, Bfl[j]);
                mma16816(C[i][j], Afh, Bfh[j]);
            }
        }

        if (kc < 23) {
            const int nxt = cur ^ 1;
            Ah[nxt][kq][rowA0] = nh0.x; Ah[nxt][kq + 1][rowA0] = nh0.y;
            Al[nxt][kq][rowA0] = nl0.x; Al[nxt][kq + 1][rowA0] = nl0.y;
            Ah[nxt][kq][rowA1] = nh1.x; Ah[nxt][kq + 1][rowA1] = nh1.y;
            Al[nxt][kq][rowA1] = nl1.x; Al[nxt][kq + 1][rowA1] = nl1.y;
            *reinterpret_cast<uint4*>(&Bh[nxt][krow][o4]) = nwh;
            *reinterpret_cast<uint4*>(&Bl[nxt][krow][o4]) = nwl;
            __syncthreads();
        }
    }

    // ---- epilogue: bias + store (fragment layout) ----
    #pragma unroll
    for (int j = 0; j < 4; ++j) {
        int col = wn * 32 + j * 8 + c2;
        float2 bv = *reinterpret_cast<const float2*>(bias + col);
        #pragma unroll
        for (int i = 0; i < 4; ++i) {
            int r = r0 + wm * 64 + i * 16 + rp;
            float2 o0, o1;
            o0.x = C[i][j][0] + bv.x; o0.y = C[i][j][1] + bv.y;
            o1.x = C[i][j][2] + bv.x; o1.y = C[i][j][3] + bv.y;
            *reinterpret_cast<float2*>(out + r * ODIM + col)       = o0;
            *reinterpret_cast<float2*>(out + (r + 8) * ODIM + col) = o1;
        }
    }
}

// ============================================================
// Launch
// ============================================================
extern "C" void kernel_launch(void* const* d_in, const int* in_sizes, int n_in,
                              void* d_out, int out_size) {
    const float* inputs = (const float*)d_in[0];
    const float* state  = (const float*)d_in[1];
    const int*   rows   = (const int*)  d_in[2];
    const int*   cols   = (const int*)  d_in[3];
    const float* vals   = (const float*)d_in[4];
    const float* weight = (const float*)d_in[5];
    const float* biases = (const float*)d_in[6];
    float* out = (float*)d_out;

    build_x0_kernel<<<(NN * ROWSZ / 4 + 255) / 256, 256>>>(inputs, state);
    build_rowptr_kernel<<<(NE + 255) / 256, 256>>>(rows);
    reorder_w_kernel<<<(KPAIRS * ODIM + 255) / 256, 256>>>(weight);
    spmm_kernel<<<NN * 2, 256>>>(cols, vals, 0);
    spmm_kernel<<<NN * 2, 256>>>(cols, vals, 1);
    gemm_kernel<<<MROWS / 128, 256>>>(biases, out);
}

// round 8
// speedup vs baseline: 1.0018x; 1.0018x over previous
#include <cuda_runtime.h>
#include <cstdint>

#define NN      10000       // nodes
#define NBATCH  16          // batch
#define FDIM    128         // feature dim (64 input + 64 hidden)
#define ROWSZ   2048        // NBATCH * FDIM, floats per node-row
#define PROWSZ  1024        // packed (bf16-pair) uints per node-row
#define NE      160000      // edges
#define ODIM    128         // output dim
#define KDIM    384         // FDIM * 3 matrices
#define KPAIRS  192         // KDIM / 2
#define MROWS   160000      // NBATCH * NN
#define INSZ    640000      // NN * 64, per-batch stride of inputs/state

// ---- scratch (static device globals; no allocation) ----
__device__ float    g_x0[NN * ROWSZ];
__device__ float    g_x1[NN * ROWSZ];
__device__ unsigned g_x0h[NN * PROWSZ];
__device__ unsigned g_x0l[NN * PROWSZ];
__device__ unsigned g_x1h[NN * PROWSZ];
__device__ unsigned g_x1l[NN * PROWSZ];
__device__ unsigned g_x2h[NN * PROWSZ];
__device__ unsigned g_x2l[NN * PROWSZ];
__device__ unsigned g_wph[KPAIRS * ODIM];
__device__ unsigned g_wpl[KPAIRS * ODIM];
__device__ int      g_rowptr[NN + 1];

// pack two fp32 (even k, odd k) into bf16x2 hi + exact-residual bf16x2 lo
__device__ __forceinline__ void pack2(float e, float o, unsigned& h, unsigned& l) {
    asm("cvt.rn.bf16x2.f32 %0, %1, %2;" : "=r"(h) : "f"(o), "f"(e));
    float he = __uint_as_float(h << 16);
    float ho = __uint_as_float(h & 0xffff0000u);
    asm("cvt.rn.bf16x2.f32 %0, %1, %2;" : "=r"(l) : "f"(o - ho), "f"(e - he));
}

// ============================================================
// Kernel 1: build x0[n][b][f] (fp32 + packed hi/lo bf16 pairs)
// ============================================================
__global__ void build_x0_kernel(const float* __restrict__ in,
                                const float* __restrict__ st) {
    int id = blockIdx.x * blockDim.x + threadIdx.x;   // float4 units
    if (id >= NN * ROWSZ / 4) return;
    int f4 = id & 31;            // 32 float4 per (n,b)
    int b  = (id >> 5) & 15;
    int n  = id >> 9;
    int f  = f4 << 2;
    const float* src = (f < 64) ? (in + b * INSZ + n * 64 + f)
                                : (st + b * INSZ + n * 64 + (f - 64));
    float4 v = *reinterpret_cast<const float4*>(src);
    reinterpret_cast<float4*>(g_x0)[id] = v;
    uint2 h, l;
    pack2(v.x, v.y, h.x, l.x);
    pack2(v.z, v.w, h.y, l.y);
    reinterpret_cast<uint2*>(g_x0h)[id] = h;
    reinterpret_cast<uint2*>(g_x0l)[id] = l;
}

// ============================================================
// Kernel 2: CSR row pointers from sorted COO rows
// ============================================================
__global__ void build_rowptr_kernel(const int* __restrict__ rows) {
    int e = blockIdx.x * blockDim.x + threadIdx.x;
    if (e >= NE) return;
    int r = rows[e];
    int rprev = (e == 0) ? -1 : rows[e - 1];
    for (int rr = rprev + 1; rr <= r; ++rr) g_rowptr[rr] = e;
    if (e == NE - 1) {
        for (int rr = r + 1; rr <= NN; ++rr) g_rowptr[rr] = NE;
    }
}

// ============================================================
// Kernel 3: weight W[f*3+m][o] -> packed W'[kp][o] hi/lo
//   k = m*128+f ; pair (2kp, 2kp+1) always within one matrix m
// ============================================================
__global__ void reorder_w_kernel(const float* __restrict__ w) {
    int id = blockIdx.x * blockDim.x + threadIdx.x;  // 192*128 = 24576
    if (id >= KPAIRS * ODIM) return;
    int o  = id & 127;
    int kp = id >> 7;            // 0..191
    int m  = kp >> 6;            // matrix
    int fe = (kp & 63) << 1;     // even feature
    float we = w[(fe * 3 + m) * ODIM + o];
    float wo = w[((fe + 1) * 3 + m) * ODIM + o];
    unsigned h, l;
    pack2(we, wo, h, l);
    g_wph[id] = h;
    g_wpl[id] = l;
}

// ============================================================
// Kernel 4: SpMM (CSR, 2 blocks per row, 256 thr x 4 floats)
//   unrolled x4, 4 accumulators (MLP=4)
//   mode 0:  x1 = S x0            -> fp32 + hi/lo
//   mode 1:  x2 = 2 S x1 - x0     -> hi/lo only
// ============================================================
__global__ __launch_bounds__(256) void spmm_kernel(const int* __restrict__ cols,
                                                   const float* __restrict__ vals,
                                                   int mode) {
    const float* __restrict__ z = mode ? g_x1 : g_x0;
    const float alpha           = mode ? 2.0f : 1.0f;

    int r    = blockIdx.x >> 1;          // node row
    int half = blockIdx.x & 1;           // which 1024-float half
    int t    = threadIdx.x + half * 256; // float4 index within row: 0..511
    int e0 = g_rowptr[r];
    int e1 = g_rowptr[r + 1];
    int base = r * ROWSZ;

    float4 a0 = make_float4(0.f, 0.f, 0.f, 0.f);
    float4 a1 = a0, a2 = a0, a3 = a0;
    if (mode) {
        float4 s = reinterpret_cast<const float4*>(g_x0 + base)[t];
        a0.x = -s.x; a0.y = -s.y; a0.z = -s.z; a0.w = -s.w;
    }

    const float4* z4 = reinterpret_cast<const float4*>(z);
    int e = e0;
    for (; e + 3 < e1; e += 4) {
        int   c0 = __ldg(&cols[e]);
        int   c1 = __ldg(&cols[e + 1]);
        int   c2 = __ldg(&cols[e + 2]);
        int   c3 = __ldg(&cols[e + 3]);
        float v0 = alpha * __ldg(&vals[e]);
        float v1 = alpha * __ldg(&vals[e + 1]);
        float v2 = alpha * __ldg(&vals[e + 2]);
        float v3 = alpha * __ldg(&vals[e + 3]);
        float4 p0 = z4[c0 * 512 + t];
        float4 p1 = z4[c1 * 512 + t];
        float4 p2 = z4[c2 * 512 + t];
        float4 p3 = z4[c3 * 512 + t];
        a0.x += v0 * p0.x; a0.y += v0 * p0.y; a0.z += v0 * p0.z; a0.w += v0 * p0.w;
        a1.x += v1 * p1.x; a1.y += v1 * p1.y; a1.z += v1 * p1.z; a1.w += v1 * p1.w;
        a2.x += v2 * p2.x; a2.y += v2 * p2.y; a2.z += v2 * p2.z; a2.w += v2 * p2.w;
        a3.x += v3 * p3.x; a3.y += v3 * p3.y; a3.z += v3 * p3.z; a3.w += v3 * p3.w;
    }
    for (; e < e1; ++e) {
        int   c0 = __ldg(&cols[e]);
        float v0 = alpha * __ldg(&vals[e]);
        float4 p0 = z4[c0 * 512 + t];
        a0.x += v0 * p0.x; a0.y += v0 * p0.y; a0.z += v0 * p0.z; a0.w += v0 * p0.w;
    }
    a0.x += a1.x + a2.x + a3.x;
    a0.y += a1.y + a2.y + a3.y;
    a0.z += a1.z + a2.z + a3.z;
    a0.w += a1.w + a2.w + a3.w;

    uint2 h, l;
    pack2(a0.x, a0.y, h.x, l.x);
    pack2(a0.z, a0.w, h.y, l.y);
    int pidx = r * (PROWSZ / 2) + t;     // uint2 index into packed row
    if (mode) {
        reinterpret_cast<uint2*>(g_x2h)[pidx] = h;
        reinterpret_cast<uint2*>(g_x2l)[pidx] = l;
    } else {
        reinterpret_cast<float4*>(g_x1 + base)[t] = a0;
        reinterpret_cast<uint2*>(g_x1h)[pidx] = h;
        reinterpret_cast<uint2*>(g_x1l)[pidx] = l;
    }
}

__device__ __forceinline__ void mma16816(float c[4], const unsigned a[4], const unsigned b[2]) {
    asm("mma.sync.aligned.m16n8k16.row.col.f32.bf16.bf16.f32 "
        "{%0,%1,%2,%3},{%4,%5,%6,%7},{%8,%9},{%0,%1,%2,%3};"
        : "+f"(c[0]), "+f"(c[1]), "+f"(c[2]), "+f"(c[3])
        : "r"(a[0]), "r"(a[1]), "r"(a[2]), "r"(a[3]), "r"(b[0]), "r"(b[1]));
}

// ============================================================
// Kernel 5: GEMM  out[r, o] = bias[o] + sum_k A[r,k] * W'[k,o]
//   BM=128 BN=128 BK=16 (8 kpairs), 256 threads (8 warps 2x4)
//   pre-split bf16 hi/lo operands, 3xMMA per tile, no cvt in loop
// ============================================================
__global__ __launch_bounds__(256) void gemm_kernel(const float* __restrict__ bias,
                                                   float* __restrict__ out) {
    __shared__ unsigned Ah[2][8][136], Al[2][8][136];   // [kpair][m], pad 136
    __shared__ unsigned Bh[2][8][136], Bl[2][8][136];   // [kpair][n]

    const int tid  = threadIdx.x;
    const int r0   = blockIdx.x * 128;
    const int lane = tid & 31;
    const int wid  = tid >> 5;
    const int wm   = wid & 1;          // warp row  (64 rows each)
    const int wn   = wid >> 1;         // warp col  (32 cols each)
    const int rp   = lane >> 2;        // 0..7
    const int kp   = lane & 3;         // kpair low index
    const int c2   = kp << 1;          // even col within k16

    // ---- staging indices ----
    const int rowA0 = tid >> 2;          // 0..63
    const int rowA1 = rowA0 + 64;
    const int kq    = (tid & 3) << 1;    // kpair offset 0,2,4,6

    int rg0 = r0 + rowA0;
    int b0  = rg0 / NN;
    int baseP0 = (rg0 - b0 * NN) * PROWSZ + b0 * 64;
    int rg1 = r0 + rowA1;
    int b1  = rg1 / NN;
    int baseP1 = (rg1 - b1 * NN) * PROWSZ + b1 * 64;

    const int krow = tid >> 5;           // 0..7 (kpair row for B)
    const int o4   = (tid & 31) << 2;    // 0..124

    float C[4][4][4];
    #pragma unroll
    for (int i = 0; i < 4; ++i)
        #pragma unroll
        for (int j = 0; j < 4; ++j)
            #pragma unroll
            for (int q = 0; q < 4; ++q)
                C[i][j][q] = 0.f;

    // ---- prologue: chunk 0 (m=0, kpair base 0) ----
    {
        uint2 h0 = *reinterpret_cast<const uint2*>(g_x0h + baseP0 + kq);
        uint2 l0 = *reinterpret_cast<const uint2*>(g_x0l + baseP0 + kq);
        uint2 h1 = *reinterpret_cast<const uint2*>(g_x0h + baseP1 + kq);
        uint2 l1 = *reinterpret_cast<const uint2*>(g_x0l + baseP1 + kq);
        Ah[0][kq][rowA0] = h0.x; Ah[0][kq + 1][rowA0] = h0.y;
        Al[0][kq][rowA0] = l0.x; Al[0][kq + 1][rowA0] = l0.y;
        Ah[0][kq][rowA1] = h1.x; Ah[0][kq + 1][rowA1] = h1.y;
        Al[0][kq][rowA1] = l1.x; Al[0][kq + 1][rowA1] = l1.y;
        uint4 wh = *reinterpret_cast<const uint4*>(g_wph + krow * ODIM + o4);
        uint4 wl = *reinterpret_cast<const uint4*>(g_wpl + krow * ODIM + o4);
        *reinterpret_cast<uint4*>(&Bh[0][krow][o4]) = wh;
        *reinterpret_cast<uint4*>(&Bl[0][krow][o4]) = wl;
    }
    __syncthreads();

    #pragma unroll 1
    for (int kc = 0; kc < 24; ++kc) {
        const int cur = kc & 1;
        uint2 nh0, nl0, nh1, nl1;
        uint4 nwh, nwl;
        if (kc < 23) {
            int kn = kc + 1;
            int m  = kn >> 3;
            int kpb = (kn & 7) << 3;           // kpair base within matrix
            const unsigned* Xh = (m == 0) ? g_x0h : (m == 1) ? g_x1h : g_x2h;
            const unsigned* Xl = (m == 0) ? g_x0l : (m == 1) ? g_x1l : g_x2l;
            nh0 = *reinterpret_cast<const uint2*>(Xh + baseP0 + kpb + kq);
            nl0 = *reinterpret_cast<const uint2*>(Xl + baseP0 + kpb + kq);
            nh1 = *reinterpret_cast<const uint2*>(Xh + baseP1 + kpb + kq);
            nl1 = *reinterpret_cast<const uint2*>(Xl + baseP1 + kpb + kq);
            int kr = (kn << 3) + krow;         // global kpair row for B
            nwh = *reinterpret_cast<const uint4*>(g_wph + kr * ODIM + o4);
            nwl = *reinterpret_cast<const uint4*>(g_wpl + kr * ODIM + o4);
        }

        // ---- B fragments (all j) ----
        unsigned Bfh[4][2], Bfl[4][2];
        #pragma unroll
        for (int j = 0; j < 4; ++j) {
            int n = wn * 32 + j * 8 + rp;
            Bfh[j][0] = Bh[cur][kp][n];     Bfh[j][1] = Bh[cur][kp + 4][n];
            Bfl[j][0] = Bl[cur][kp][n];     Bfl[j][1] = Bl[cur][kp + 4][n];
        }

        // ---- per-i: A fragment + 3xMMA row ----
        #pragma unroll
        for (int i = 0; i < 4; ++i) {
            int r = wm * 64 + i * 16 + rp;
            unsigned Afh[4], Afl[4];
            Afh[0] = Ah[cur][kp][r];      Afh[1] = Ah[cur][kp][r + 8];
            Afh[2] = Ah[cur][kp + 4][r];  Afh[3] = Ah[cur][kp + 4][r + 8];
            Afl[0] = Al[cur][kp][r];      Afl[1] = Al[cur][kp][r + 8];
            Afl[2] = Al[cur][kp + 4][r];  Afl[3] = Al[cur][kp + 4][r + 8];
            #pragma unroll
            for (int j = 0; j < 4; ++j) {
                mma16816(C[i][j], Afl, Bfh[j]);
                mma16816(C[i][j], Afh, Bfl[j]);
                mma16816(C[i][j], Afh, Bfh[j]);
            }
        }

        if (kc < 23) {
            const int nxt = cur ^ 1;
            Ah[nxt][kq][rowA0] = nh0.x; Ah[nxt][kq + 1][rowA0] = nh0.y;
            Al[nxt][kq][rowA0] = nl0.x; Al[nxt][kq + 1][rowA0] = nl0.y;
            Ah[nxt][kq][rowA1] = nh1.x; Ah[nxt][kq + 1][rowA1] = nh1.y;
            Al[nxt][kq][rowA1] = nl1.x; Al[nxt][kq + 1][rowA1] = nl1.y;
            *reinterpret_cast<uint4*>(&Bh[nxt][krow][o4]) = nwh;
            *reinterpret_cast<uint4*>(&Bl[nxt][krow][o4]) = nwl;
            __syncthreads();
        }
    }

    // ---- epilogue: bias + store (fragment layout) ----
    #pragma unroll
    for (int j = 0; j < 4; ++j) {
        int col = wn * 32 + j * 8 + c2;
        float2 bv = *reinterpret_cast<const float2*>(bias + col);
        #pragma unroll
        for (int i = 0; i < 4; ++i) {
            int r = r0 + wm * 64 + i * 16 + rp;
            float2 o0, o1;
            o0.x = C[i][j][0] + bv.x; o0.y = C[i][j][1] + bv.y;
            o1.x = C[i][j][2] + bv.x; o1.y = C[i][j][3] + bv.y;
            *reinterpret_cast<float2*>(out + r * ODIM + col)       = o0;
            *reinterpret_cast<float2*>(out + (r + 8) * ODIM + col) = o1;
        }
    }
}

// ============================================================
// Launch
// ============================================================
extern "C" void kernel_launch(void* const* d_in, const int* in_sizes, int n_in,
                              void* d_out, int out_size) {
    const float* inputs = (const float*)d_in[0];
    const float* state  = (const float*)d_in[1];
    const int*   rows   = (const int*)  d_in[2];
    const int*   cols   = (const int*)  d_in[3];
    const float* vals   = (const float*)d_in[4];
    const float* weight = (const float*)d_in[5];
    const float* biases = (const float*)d_in[6];
    float* out = (float*)d_out;

    build_x0_kernel<<<(NN * ROWSZ / 4 + 255) / 256, 256>>>(inputs, state);
    build_rowptr_kernel<<<(NE + 255) / 256, 256>>>(rows);
    reorder_w_kernel<<<(KPAIRS * ODIM + 255) / 256, 256>>>(weight);
    spmm_kernel<<<NN * 2, 256>>>(cols, vals, 0);
    spmm_kernel<<<NN * 2, 256>>>(cols, vals, 1);
    gemm_kernel<<<MROWS / 128, 256>>>(biases, out);
}

// round 9
// speedup vs baseline: 1.1431x; 1.1411x over previous
#include <cuda_runtime.h>
#include <cstdint>

#define NN      10000       // nodes
#define NBATCH  16          // batch
#define FDIM    128         // feature dim (64 input + 64 hidden)
#define ROWSZ   2048        // NBATCH * FDIM, floats per node-row
#define PROWSZ  1024        // packed (bf16-pair) uints per node-row
#define NE      160000      // edges
#define ODIM    128         // output dim
#define KDIM    384         // FDIM * 3 matrices
#define KPAIRS  192         // KDIM / 2
#define MROWS   160000      // NBATCH * NN
#define INSZ    640000      // NN * 64, per-batch stride of inputs/state

// ---- scratch (static device globals; no allocation) ----
__device__ float    g_x0[NN * ROWSZ];
__device__ float    g_x1[NN * ROWSZ];
__device__ unsigned g_x0h[NN * PROWSZ];
__device__ unsigned g_x0l[NN * PROWSZ];
__device__ unsigned g_x1h[NN * PROWSZ];
__device__ unsigned g_x1l[NN * PROWSZ];
__device__ unsigned g_x2h[NN * PROWSZ];
__device__ unsigned g_x2l[NN * PROWSZ];
__device__ unsigned g_wph[KPAIRS * ODIM];
__device__ unsigned g_wpl[KPAIRS * ODIM];
__device__ int      g_rowptr[NN + 1];

// pack two fp32 (even k, odd k) into bf16x2 hi + exact-residual bf16x2 lo
__device__ __forceinline__ void pack2(float e, float o, unsigned& h, unsigned& l) {
    asm("cvt.rn.bf16x2.f32 %0, %1, %2;" : "=r"(h) : "f"(o), "f"(e));
    float he = __uint_as_float(h << 16);
    float ho = __uint_as_float(h & 0xffff0000u);
    asm("cvt.rn.bf16x2.f32 %0, %1, %2;" : "=r"(l) : "f"(o - ho), "f"(e - he));
}

// ============================================================
// Kernel 1: build x0[n][b][f] (fp32 + packed hi/lo bf16 pairs)
// ============================================================
__global__ void build_x0_kernel(const float* __restrict__ in,
                                const float* __restrict__ st) {
    int id = blockIdx.x * blockDim.x + threadIdx.x;   // float4 units
    if (id >= NN * ROWSZ / 4) return;
    int f4 = id & 31;            // 32 float4 per (n,b)
    int b  = (id >> 5) & 15;
    int n  = id >> 9;
    int f  = f4 << 2;
    const float* src = (f < 64) ? (in + b * INSZ + n * 64 + f)
                                : (st + b * INSZ + n * 64 + (f - 64));
    float4 v = *reinterpret_cast<const float4*>(src);
    reinterpret_cast<float4*>(g_x0)[id] = v;
    uint2 h, l;
    pack2(v.x, v.y, h.x, l.x);
    pack2(v.z, v.w, h.y, l.y);
    reinterpret_cast<uint2*>(g_x0h)[id] = h;
    reinterpret_cast<uint2*>(g_x0l)[id] = l;
}

// ============================================================
// Kernel 2: CSR row pointers from sorted COO rows
// ============================================================
__global__ void build_rowptr_kernel(const int* __restrict__ rows) {
    int e = blockIdx.x * blockDim.x + threadIdx.x;
    if (e >= NE) return;
    int r = rows[e];
    int rprev = (e == 0) ? -1 : rows[e - 1];
    for (int rr = rprev + 1; rr <= r; ++rr) g_rowptr[rr] = e;
    if (e == NE - 1) {
        for (int rr = r + 1; rr <= NN; ++rr) g_rowptr[rr] = NE;
    }
}

// ============================================================
// Kernel 3: weight W[f*3+m][o] -> packed W'[kp][o] hi/lo
// ============================================================
__global__ void reorder_w_kernel(const float* __restrict__ w) {
    int id = blockIdx.x * blockDim.x + threadIdx.x;  // 192*128 = 24576
    if (id >= KPAIRS * ODIM) return;
    int o  = id & 127;
    int kp = id >> 7;            // 0..191
    int m  = kp >> 6;            // matrix
    int fe = (kp & 63) << 1;     // even feature
    float we = w[(fe * 3 + m) * ODIM + o];
    float wo = w[((fe + 1) * 3 + m) * ODIM + o];
    unsigned h, l;
    pack2(we, wo, h, l);
    g_wph[id] = h;
    g_wpl[id] = l;
}

// ============================================================
// Kernel 4: SpMM (CSR, 2 blocks per row, 256 thr x 4 floats)
//   x2 unroll, 2 accumulators; occupancy pinned (<=32 regs)
//   mode 0:  x1 = S x0            -> fp32 + hi/lo
//   mode 1:  x2 = 2 S x1 - x0     -> hi/lo only
// ============================================================
__global__ __launch_bounds__(256, 8) void spmm_kernel(const int* __restrict__ cols,
                                                      const float* __restrict__ vals,
                                                      int mode) {
    const float* __restrict__ z = mode ? g_x1 : g_x0;
    const float alpha           = mode ? 2.0f : 1.0f;

    int r    = blockIdx.x >> 1;          // node row
    int half = blockIdx.x & 1;           // which 1024-float half
    int t    = threadIdx.x + half * 256; // float4 index within row: 0..511
    int e0 = g_rowptr[r];
    int e1 = g_rowptr[r + 1];
    int base = r * ROWSZ;

    float4 a0 = make_float4(0.f, 0.f, 0.f, 0.f);
    float4 a1 = a0;
    if (mode) {
        float4 s = reinterpret_cast<const float4*>(g_x0 + base)[t];
        a0.x = -s.x; a0.y = -s.y; a0.z = -s.z; a0.w = -s.w;
    }

    const float4* z4 = reinterpret_cast<const float4*>(z);
    int e = e0;
    for (; e + 1 < e1; e += 2) {
        int   c0 = __ldg(&cols[e]);
        int   c1 = __ldg(&cols[e + 1]);
        float v0 = alpha * __ldg(&vals[e]);
        float v1 = alpha * __ldg(&vals[e + 1]);
        float4 p0 = z4[c0 * 512 + t];
        float4 p1 = z4[c1 * 512 + t];
        a0.x += v0 * p0.x; a0.y += v0 * p0.y; a0.z += v0 * p0.z; a0.w += v0 * p0.w;
        a1.x += v1 * p1.x; a1.y += v1 * p1.y; a1.z += v1 * p1.z; a1.w += v1 * p1.w;
    }
    if (e < e1) {
        int   c0 = __ldg(&cols[e]);
        float v0 = alpha * __ldg(&vals[e]);
        float4 p0 = z4[c0 * 512 + t];
        a0.x += v0 * p0.x; a0.y += v0 * p0.y; a0.z += v0 * p0.z; a0.w += v0 * p0.w;
    }
    a0.x += a1.x; a0.y += a1.y; a0.z += a1.z; a0.w += a1.w;

    uint2 h, l;
    pack2(a0.x, a0.y, h.x, l.x);
    pack2(a0.z, a0.w, h.y, l.y);
    int pidx = r * (PROWSZ / 2) + t;     // uint2 index into packed row
    if (mode) {
        reinterpret_cast<uint2*>(g_x2h)[pidx] = h;
        reinterpret_cast<uint2*>(g_x2l)[pidx] = l;
    } else {
        reinterpret_cast<float4*>(g_x1 + base)[t] = a0;
        reinterpret_cast<uint2*>(g_x1h)[pidx] = h;
        reinterpret_cast<uint2*>(g_x1l)[pidx] = l;
    }
}

__device__ __forceinline__ void mma16816(float c[4], const unsigned a[4], const unsigned b[2]) {
    asm("mma.sync.aligned.m16n8k16.row.col.f32.bf16.bf16.f32 "
        "{%0,%1,%2,%3},{%4,%5,%6,%7},{%8,%9},{%0,%1,%2,%3};"
        : "+f"(c[0]), "+f"(c[1]), "+f"(c[2]), "+f"(c[3])
        : "r"(a[0]), "r"(a[1]), "r"(a[2]), "r"(a[3]), "r"(b[0]), "r"(b[1]));
}

// ============================================================
// Kernel 5: GEMM  out[r, o] = bias[o] + sum_k A[r,k] * W'[k,o]
//   BM=128 BN=128 BK=16 (8 kpairs), 256 threads (8 warps 2x4)
//   pre-split bf16 hi/lo operands, 3xMMA per tile, no cvt in loop
// ============================================================
__global__ __launch_bounds__(256) void gemm_kernel(const float* __restrict__ bias,
                                                   float* __restrict__ out) {
    __shared__ unsigned Ah[2][8][136], Al[2][8][136];   // [kpair][m], pad 136
    __shared__ unsigned Bh[2][8][136], Bl[2][8][136];   // [kpair][n]

    const int tid  = threadIdx.x;
    const int r0   = blockIdx.x * 128;
    const int lane = tid & 31;
    const int wid  = tid >> 5;
    const int wm   = wid & 1;          // warp row  (64 rows each)
    const int wn   = wid >> 1;         // warp col  (32 cols each)
    const int rp   = lane >> 2;        // 0..7
    const int kp   = lane & 3;         // kpair low index
    const int c2   = kp << 1;          // even col within k16

    // ---- staging indices ----
    const int rowA0 = tid >> 2;          // 0..63
    const int rowA1 = rowA0 + 64;
    const int kq    = (tid & 3) << 1;    // kpair offset 0,2,4,6

    int rg0 = r0 + rowA0;
    int b0  = rg0 / NN;
    int baseP0 = (rg0 - b0 * NN) * PROWSZ + b0 * 64;
    int rg1 = r0 + rowA1;
    int b1  = rg1 / NN;
    int baseP1 = (rg1 - b1 * NN) * PROWSZ + b1 * 64;

    const int krow = tid >> 5;           // 0..7 (kpair row for B)
    const int o4   = (tid & 31) << 2;    // 0..124

    float C[4][4][4];
    #pragma unroll
    for (int i = 0; i < 4; ++i)
        #pragma unroll
        for (int j = 0; j < 4; ++j)
            #pragma unroll
            for (int q = 0; q < 4; ++q)
                C[i][j][q] = 0.f;

    // ---- prologue: chunk 0 (m=0, kpair base 0) ----
    {
        uint2 h0 = *reinterpret_cast<const uint2*>(g_x0h + baseP0 + kq);
        uint2 l0 = *reinterpret_cast<const uint2*>(g_x0l + baseP0 + kq);
        uint2 h1 = *reinterpret_cast<const uint2*>(g_x0h + baseP1 + kq);
        uint2 l1 = *reinterpret_cast<const uint2*>(g_x0l + baseP1 + kq);
        Ah[0][kq][rowA0] = h0.x; Ah[0][kq + 1][rowA0] = h0.y;
        Al[0][kq][rowA0] = l0.x; Al[0][kq + 1][rowA0] = l0.y;
        Ah[0][kq][rowA1] = h1.x; Ah[0][kq + 1][rowA1] = h1.y;
        Al[0][kq][rowA1] = l1.x; Al[0][kq + 1][rowA1] = l1.y;
        uint4 wh = *reinterpret_cast<const uint4*>(g_wph + krow * ODIM + o4);
        uint4 wl = *reinterpret_cast<const uint4*>(g_wpl + krow * ODIM + o4);
        *reinterpret_cast<uint4*>(&Bh[0][krow][o4]) = wh;
        *reinterpret_cast<uint4*>(&Bl[0][krow][o4]) = wl;
    }
    __syncthreads();

    #pragma unroll 1
    for (int kc = 0; kc < 24; ++kc) {
        const int cur = kc & 1;
        uint2 nh0, nl0, nh1, nl1;
        uint4 nwh, nwl;
        if (kc < 23) {
            int kn = kc + 1;
            int m  = kn >> 3;
            int kpb = (kn & 7) << 3;           // kpair base within matrix
            const unsigned* Xh = (m == 0) ? g_x0h : (m == 1) ? g_x1h : g_x2h;
            const unsigned* Xl = (m == 0) ? g_x0l : (m == 1) ? g_x1l : g_x2l;
            nh0 = *reinterpret_cast<const uint2*>(Xh + baseP0 + kpb + kq);
            nl0 = *reinterpret_cast<const uint2*>(Xl + baseP0 + kpb + kq);
            nh1 = *reinterpret_cast<const uint2*>(Xh + baseP1 + kpb + kq);
            nl1 = *reinterpret_cast<const uint2*>(Xl + baseP1 + kpb + kq);
            int kr = (kn << 3) + krow;         // global kpair row for B
            nwh = *reinterpret_cast<const uint4*>(g_wph + kr * ODIM + o4);
            nwl = *reinterpret_cast<const uint4*>(g_wpl + kr * ODIM + o4);
        }

        // ---- B fragments (all j) ----
        unsigned Bfh[4][2], Bfl[4][2];
        #pragma unroll
        for (int j = 0; j < 4; ++j) {
            int n = wn * 32 + j * 8 + rp;
            Bfh[j][0] = Bh[cur][kp][n];     Bfh[j][1] = Bh[cur][kp + 4][n];
            Bfl[j][0] = Bl[cur][kp][n];     Bfl[j][1] = Bl[cur][kp + 4][n];
        }

        // ---- per-i: A fragment + 3xMMA row ----
        #pragma unroll
        for (int i = 0; i < 4; ++i) {
            int r = wm * 64 + i * 16 + rp;
            unsigned Afh[4], Afl[4];
            Afh[0] = Ah[cur][kp][r];      Afh[1] = Ah[cur][kp][r + 8];
            Afh[2] = Ah[cur][kp + 4][r];  Afh[3] = Ah[cur][kp + 4][r + 8];
            Afl[0] = Al[cur][kp][r];      Afl[1] = Al[cur][kp][r + 8];
            Afl[2] = Al[cur][kp + 4][r];  Afl[3] = Al[cur][kp + 4][r + 8];
            #pragma unroll
            for (int j = 0; j < 4; ++j) {
                mma16816(C[i][j], Afl, Bfh[j]);
                mma16816(C[i][j], Afh, Bfl[j]);
                mma16816(C[i][j], Afh, Bfh[j]);
            }
        }

        if (kc < 23) {
            const int nxt = cur ^ 1;
            Ah[nxt][kq][rowA0] = nh0.x; Ah[nxt][kq + 1][rowA0] = nh0.y;
            Al[nxt][kq][rowA0] = nl0.x; Al[nxt][kq + 1][rowA0] = nl0.y;
            Ah[nxt][kq][rowA1] = nh1.x; Ah[nxt][kq + 1][rowA1] = nh1.y;
            Al[nxt][kq][rowA1] = nl1.x; Al[nxt][kq + 1][rowA1] = nl1.y;
            *reinterpret_cast<uint4*>(&Bh[nxt][krow][o4]) = nwh;
            *reinterpret_cast<uint4*>(&Bl[nxt][krow][o4]) = nwl;
            __syncthreads();
        }
    }

    // ---- epilogue: bias + store (fragment layout) ----
    #pragma unroll
    for (int j = 0; j < 4; ++j) {
        int col = wn * 32 + j * 8 + c2;
        float2 bv = *reinterpret_cast<const float2*>(bias + col);
        #pragma unroll
        for (int i = 0; i < 4; ++i) {
            int r = r0 + wm * 64 + i * 16 + rp;
            float2 o0, o1;
            o0.x = C[i][j][0] + bv.x; o0.y = C[i][j][1] + bv.y;
            o1.x = C[i][j][2] + bv.x; o1.y = C[i][j][3] + bv.y;
            *reinterpret_cast<float2*>(out + r * ODIM + col)       = o0;
            *reinterpret_cast<float2*>(out + (r + 8) * ODIM + col) = o1;
        }
    }
}

// ============================================================
// Launch
// ============================================================
extern "C" void kernel_launch(void* const* d_in, const int* in_sizes, int n_in,
                              void* d_out, int out_size) {
    const float* inputs = (const float*)d_in[0];
    const float* state  = (const float*)d_in[1];
    const int*   rows   = (const int*)  d_in[2];
    const int*   cols   = (const int*)  d_in[3];
    const float* vals   = (const float*)d_in[4];
    const float* weight = (const float*)d_in[5];
    const float* biases = (const float*)d_in[6];
    float* out = (float*)d_out;

    build_x0_kernel<<<(NN * ROWSZ / 4 + 255) / 256, 256>>>(inputs, state);
    build_rowptr_kernel<<<(NE + 255) / 256, 256>>>(rows);
    reorder_w_kernel<<<(KPAIRS * ODIM + 255) / 256, 256>>>(weight);
    spmm_kernel<<<NN * 2, 256>>>(cols, vals, 0);
    spmm_kernel<<<NN * 2, 256>>>(cols, vals, 1);
    gemm_kernel<<<MROWS / 128, 256>>>(biases, out);
}